// round 14
// baseline (speedup 1.0000x reference)
#include <cuda_runtime.h>
#include <cuda_bf16.h>
#include <cstdint>

#define BATCH 64
#define SEQ   512
#define DIN   256
#define UNITS 512
#define M_TOT (BATCH * SEQ)   // 32768

// M split: tensor rows [0, ROWS_T), fp32 rows [ROWS_T, 32768)
#define ROWS_T   17408        // 136 Mtiles of 128
#define T_TILESQ 1088         // 136 * 8  (N tiles of 64)
#define F_TILESQ 960          // 120 * 8  (N tiles of 64)

// ---------------- scratch (module-static, no allocation APIs) ----------------
__device__ float         g_xT[(size_t)M_TOT * UNITS];    // 64 MB
__device__ __nv_bfloat16 g_Ah[(size_t)ROWS_T * DIN];     // tensor-share A split
__device__ __nv_bfloat16 g_Al[(size_t)ROWS_T * DIN];
__device__ __nv_bfloat16 g_Bh[(size_t)UNITS * DIN];      // [N][K] (T transposed)
__device__ __nv_bfloat16 g_Bl[(size_t)UNITS * DIN];
__device__ int           g_qT, g_qF;                     // tile queues

// ---------------- PTX helpers ----------------
static __device__ __forceinline__ uint32_t smem_u32(const void* p) {
    uint32_t a;
    asm("{ .reg .u64 t; cvta.to.shared.u64 t, %1; cvt.u32.u64 %0, t; }" : "=r"(a) : "l"(p));
    return a;
}
static __device__ __forceinline__ void cp16(uint32_t dst, const void* src) {
    asm volatile("cp.async.cg.shared.global [%0], [%1], 16;" :: "r"(dst), "l"(src));
}
static __device__ __forceinline__ void cp_commit() { asm volatile("cp.async.commit_group;"); }
template <int N> static __device__ __forceinline__ void cp_wait() {
    asm volatile("cp.async.wait_group %0;" :: "n"(N));
}
static __device__ __forceinline__ void ldmx4(uint32_t& r0, uint32_t& r1,
                                             uint32_t& r2, uint32_t& r3, uint32_t addr) {
    asm volatile("ldmatrix.sync.aligned.m8n8.x4.shared.b16 {%0,%1,%2,%3}, [%4];"
                 : "=r"(r0), "=r"(r1), "=r"(r2), "=r"(r3) : "r"(addr));
}
static __device__ __forceinline__ void mma16816(float* c, const uint32_t* a,
                                                uint32_t b0, uint32_t b1) {
    asm volatile(
        "mma.sync.aligned.m16n8k16.row.col.f32.bf16.bf16.f32 "
        "{%0,%1,%2,%3}, {%4,%5,%6,%7}, {%8,%9}, {%0,%1,%2,%3};"
        : "+f"(c[0]), "+f"(c[1]), "+f"(c[2]), "+f"(c[3])
        : "r"(a[0]), "r"(a[1]), "r"(a[2]), "r"(a[3]), "r"(b0), "r"(b1));
}
static __device__ __forceinline__ uint32_t sw_addr(uint32_t base, int row, int colb) {
    return base + (uint32_t)(row * 128) + (uint32_t)(colb ^ ((row & 7) << 4));
}
// packed f32x2 FFMA2 helpers
static __device__ __forceinline__ unsigned long long pack2(float x, float y) {
    unsigned long long r;
    asm("mov.b64 %0, {%1, %2};" : "=l"(r) : "f"(x), "f"(y));
    return r;
}
static __device__ __forceinline__ void fma2(unsigned long long& d,
                                            unsigned long long a, unsigned long long b) {
    asm("fma.rn.f32x2 %0, %1, %2, %0;" : "+l"(d) : "l"(a), "l"(b));
}
static __device__ __forceinline__ void unpack2(unsigned long long v, float& x, float& y) {
    asm("mov.b64 {%0, %1}, %2;" : "=f"(x), "=f"(y) : "l"(v));
}

// ---------------- conversion kernels (tensor rows only) ----------------
__global__ __launch_bounds__(256)
void convert_x_kernel(const float* __restrict__ x) {
    size_t i4 = (size_t)blockIdx.x * 256 + threadIdx.x;   // 4-element groups
    float4 v = ((const float4*)x)[i4];
    float vv[4] = {v.x, v.y, v.z, v.w};
    unsigned short hs[4], ls[4];
#pragma unroll
    for (int j = 0; j < 4; j++) {
        __nv_bfloat16 h = __float2bfloat16_rn(vv[j]);
        __nv_bfloat16 l = __float2bfloat16_rn(vv[j] - __bfloat162float(h));
        hs[j] = *reinterpret_cast<unsigned short*>(&h);
        ls[j] = *reinterpret_cast<unsigned short*>(&l);
    }
    ((uint2*)g_Ah)[i4] = make_uint2((uint32_t)hs[0] | ((uint32_t)hs[1] << 16),
                                    (uint32_t)hs[2] | ((uint32_t)hs[3] << 16));
    ((uint2*)g_Al)[i4] = make_uint2((uint32_t)ls[0] | ((uint32_t)ls[1] << 16),
                                    (uint32_t)ls[2] | ((uint32_t)ls[3] << 16));
}

__global__ __launch_bounds__(256)
void convert_T_kernel(const float* __restrict__ T) {
    if (blockIdx.x == 0 && threadIdx.x == 0) { g_qT = 0; g_qF = 0; }
    int idx = blockIdx.x * 256 + threadIdx.x;   // idx = k*512 + n
    int k = idx >> 9;
    int n = idx & 511;
    float v = T[idx];
    __nv_bfloat16 h = __float2bfloat16_rn(v);
    __nv_bfloat16 l = __float2bfloat16_rn(v - __bfloat162float(h));
    g_Bh[(size_t)n * DIN + k] = h;
    g_Bl[(size_t)n * DIN + k] = l;
}

// ================= persistent pipe-parallel GEMM =================
// 296 CTAs: bids 0..147 = tensor role (one per SM via LUT_classic), bids
// 148..295 = fp32 role (second CTA on the SAME SMs). Each SM hosts exactly
// one of each -> tensor pipe and fma pipe run concurrently, stably.
#define TS_STAGE 49152   // Ah@0(16K), Al@16K, Bh@32K(8K), Bl@40K

// ---- tensor tile: 128(M) x 64(N), BK=64, 2-stage cp.async, 8 warps 4m x 2n ----
static __device__ void tensor_tile(int t_idx, char* sm) {
    const uint32_t sbase = smem_u32(sm);
    const int tid = threadIdx.x;
    const int wid = tid >> 5, lid = tid & 31;
    const int m0 = (t_idx >> 3) * 128;
    const int n0 = (t_idx & 7) * 64;
    const int warp_m = wid & 3;
    const int warp_n = wid >> 2;
    const int lrow = lid & 15;
    const int lqc  = (lid >> 4) * 16;
    const int arow0 = warp_m * 32 + lrow;
    const int brow0 = warp_n * 32 + lrow;

#define T_LOAD(kc) do {                                                          \
        const uint32_t _sb = sbase + ((kc) & 1) * TS_STAGE;                      \
        const int _k0 = (kc) * 64;                                               \
        _Pragma("unroll")                                                        \
        for (int i = 0; i < 8; i++) {                                            \
            int u = tid + i * 256;                                               \
            int ku = u & 7, row = (u >> 3) & 127, hl = u >> 10;                  \
            const __nv_bfloat16* g = hl ? g_Al : g_Ah;                           \
            cp16(sw_addr(_sb + hl * 16384, row, ku * 16),                        \
                 g + (size_t)(m0 + row) * DIN + _k0 + ku * 8);                   \
        }                                                                        \
        _Pragma("unroll")                                                        \
        for (int i = 0; i < 4; i++) {                                            \
            int u = tid + i * 256;                                               \
            int ku = u & 7, row = (u >> 3) & 63, hl = u >> 9;                    \
            const __nv_bfloat16* g = hl ? g_Bl : g_Bh;                           \
            cp16(sw_addr(_sb + 32768 + hl * 8192, row, ku * 16),                 \
                 g + (size_t)(n0 + row) * DIN + _k0 + ku * 8);                   \
        }                                                                        \
        cp_commit();                                                             \
    } while (0)

    float acc[2][4][4];
#pragma unroll
    for (int i = 0; i < 2; i++)
#pragma unroll
        for (int j = 0; j < 4; j++)
#pragma unroll
            for (int q = 0; q < 4; q++) acc[i][j][q] = 0.0f;

    T_LOAD(0);
    T_LOAD(1);

#pragma unroll
    for (int kc = 0; kc < 4; kc++) {
        if (kc < 3) cp_wait<1>(); else cp_wait<0>();
        __syncthreads();
        const uint32_t sb = sbase + (kc & 1) * TS_STAGE;
        // pass 0: Ah*Bh, 1: Ah*Bl, 2: Al*Bh
        const uint32_t aB[3] = {sb, sb, sb + 16384};
        const uint32_t bB[3] = {sb + 32768, sb + 40960, sb + 32768};

#pragma unroll
        for (int s = 0; s < 12; s++) {
            const uint32_t aS = aB[s >> 2], bS = bB[s >> 2];
            const int kb = (s & 3) * 32 + lqc;
            uint32_t af[2][4], bfr[4][2];
#pragma unroll
            for (int mt = 0; mt < 2; mt++)
                ldmx4(af[mt][0], af[mt][1], af[mt][2], af[mt][3],
                      sw_addr(aS, arow0 + mt * 16, kb));
#pragma unroll
            for (int ng = 0; ng < 2; ng++) {
                uint32_t r0, r1, r2, r3;
                ldmx4(r0, r1, r2, r3, sw_addr(bS, brow0 + ng * 16, kb));
                bfr[2 * ng][0] = r0; bfr[2 * ng + 1][0] = r1;
                bfr[2 * ng][1] = r2; bfr[2 * ng + 1][1] = r3;
            }
#pragma unroll
            for (int mt = 0; mt < 2; mt++)
#pragma unroll
                for (int nt = 0; nt < 4; nt++)
                    mma16816(acc[mt][nt], af[mt], bfr[nt][0], bfr[nt][1]);
        }
        __syncthreads();
        if (kc < 2) T_LOAD(kc + 2);
    }
#undef T_LOAD

    const int gID = lid >> 2, tg = lid & 3;
#pragma unroll
    for (int mt = 0; mt < 2; mt++) {
#pragma unroll
        for (int nt = 0; nt < 4; nt++) {
            int m_lo = m0 + warp_m * 32 + mt * 16 + gID;
            int n    = n0 + warp_n * 32 + nt * 8 + tg * 2;
            *(float2*)(g_xT + (size_t)m_lo * UNITS + n) =
                make_float2(acc[mt][nt][0], acc[mt][nt][1]);
            *(float2*)(g_xT + (size_t)(m_lo + 8) * UNITS + n) =
                make_float2(acc[mt][nt][2], acc[mt][nt][3]);
        }
    }
}

// ---- fp32 tile: 128(M) x 64(N), BK=16, FFMA2, exact fp32 (reads x/T directly) ----
static __device__ void fp32_tile(int f_idx, char* sm,
                                 const float* __restrict__ A, const float* __restrict__ Bm) {
    float* As = (float*)sm;                      // [16][132] transposed
    float* Bs = (float*)(sm + 16 * 132 * 4);     // [16][64]

    const int tid = threadIdx.x;
    const int m0  = ROWS_T + (f_idx >> 3) * 128;
    const int n0  = (f_idx & 7) * 64;
    const int tm0 = (tid >> 4) * 8;              // 16 groups x 8 rows
    const int tn0 = (tid & 15) * 4;              // 16 groups x 4 cols

    unsigned long long acc[8][2];
#pragma unroll
    for (int i = 0; i < 8; i++) { acc[i][0] = 0ull; acc[i][1] = 0ull; }

    for (int k0 = 0; k0 < DIN; k0 += 16) {
#pragma unroll
        for (int s = tid; s < 512; s += 256) {
            int row = s >> 2;
            int c4  = s & 3;
            float4 v = *(const float4*)(A + (size_t)(m0 + row) * DIN + k0 + c4 * 4);
            As[(c4 * 4 + 0) * 132 + row] = v.x;
            As[(c4 * 4 + 1) * 132 + row] = v.y;
            As[(c4 * 4 + 2) * 132 + row] = v.z;
            As[(c4 * 4 + 3) * 132 + row] = v.w;
        }
        {
            int kk = tid >> 4, c4 = tid & 15;
            *(float4*)(Bs + kk * 64 + c4 * 4) =
                *(const float4*)(Bm + (size_t)(k0 + kk) * UNITS + n0 + c4 * 4);
        }
        __syncthreads();

#pragma unroll
        for (int kk = 0; kk < 16; kk++) {
            float4 bv = *(const float4*)(Bs + kk * 64 + tn0);
            unsigned long long bb0 = pack2(bv.x, bv.y);
            unsigned long long bb1 = pack2(bv.z, bv.w);
            float4 a0 = *(const float4*)(As + kk * 132 + tm0);
            float4 a1 = *(const float4*)(As + kk * 132 + tm0 + 4);
            float av[8] = {a0.x, a0.y, a0.z, a0.w, a1.x, a1.y, a1.z, a1.w};
#pragma unroll
            for (int i = 0; i < 8; i++) {
                unsigned long long aa = pack2(av[i], av[i]);
                fma2(acc[i][0], aa, bb0);
                fma2(acc[i][1], aa, bb1);
            }
        }
        __syncthreads();
    }

#pragma unroll
    for (int i = 0; i < 8; i++) {
        float o[4];
        unpack2(acc[i][0], o[0], o[1]);
        unpack2(acc[i][1], o[2], o[3]);
        *(float4*)(g_xT + (size_t)(m0 + tm0 + i) * UNITS + n0 + tn0) =
            make_float4(o[0], o[1], o[2], o[3]);
    }
}

__global__ __launch_bounds__(256, 2)
void gemm_persist_kernel(const float* __restrict__ x, const float* __restrict__ T) {
    extern __shared__ __align__(1024) char sm[];
    __shared__ int s_tile;
    const bool is_tensor = (blockIdx.x < 148);

    for (;;) {
        if (threadIdx.x == 0)
            s_tile = atomicAdd(is_tensor ? &g_qT : &g_qF, 1);
        __syncthreads();
        int t = s_tile;
        __syncthreads();
        if (is_tensor) {
            if (t >= T_TILESQ) break;
            tensor_tile(t, sm);
        } else {
            if (t >= F_TILESQ) break;
            fp32_tile(t, sm, x, T);
        }
    }
}

// ---------------- scan kernel (R8-proven): smem-staged 2x2-block recurrence ----------------
__global__ __launch_bounds__(64, 1)
void scan_kernel(const float* __restrict__ Bfull, const float* __restrict__ bias,
                 const float* __restrict__ h0, float* __restrict__ out) {
    extern __shared__ __align__(1024) char sm[];   // 4 x 16KB
    const uint32_t sbase = smem_u32(sm);
    const int tid = threadIdx.x;
    const int b = blockIdx.y;
    const int u0 = blockIdx.x * 128;
    const int u = u0 + 2 * tid;

    const float B00 = Bfull[(size_t)u * UNITS + u];
    const float B01 = Bfull[(size_t)u * UNITS + u + 1];
    const float B10 = Bfull[(size_t)(u + 1) * UNITS + u];
    const float B11 = Bfull[(size_t)(u + 1) * UNITS + u + 1];
    const float2 bi = *(const float2*)(bias + u);
    float2 h = *(const float2*)(h0 + u);

    const float* xbase = g_xT + (size_t)b * SEQ * UNITS + u0;

#define SCAN_LOAD(tc) do {                                                       \
        uint32_t dst = sbase + ((tc) & 3) * 16384;                               \
        const float* src = xbase + (size_t)(tc) * 32 * UNITS;                    \
        _Pragma("unroll")                                                        \
        for (int i = 0; i < 16; i++) {                                           \
            int uq = tid + i * 64;                                               \
            int row = uq >> 5, cu = uq & 31;                                     \
            cp16(dst + row * 512 + cu * 16, src + (size_t)row * UNITS + cu * 4); \
        }                                                                        \
        cp_commit();                                                             \
    } while (0)

    SCAN_LOAD(0);
    SCAN_LOAD(1);
    SCAN_LOAD(2);
    SCAN_LOAD(3);

    float2* op = (float2*)(out + (size_t)b * UNITS + u0) + tid;

    for (int tc = 0; tc < 16; tc++) {
        if (tc < 12) cp_wait<3>(); else cp_wait<0>();
        __syncthreads();
        const float2* xs = (const float2*)(sm + (tc & 3) * 16384) + tid;
#pragma unroll
        for (int lt = 0; lt < 32; lt++) {
            float2 xv = xs[lt * 64];
            float z0 = fmaf(h.y, B10, fmaf(h.x, B00, xv.x));
            float z1 = fmaf(h.y, B11, fmaf(h.x, B01, xv.y));
            float m0 = fmaxf(fabsf(z0) + bi.x, 0.0f);
            float m1 = fmaxf(fabsf(z1) + bi.y, 0.0f);
            h.x = (z0 > 0.0f) ? m0 : ((z0 < 0.0f) ? -m0 : 0.0f);
            h.y = (z1 > 0.0f) ? m1 : ((z1 < 0.0f) ? -m1 : 0.0f);
            op[(size_t)(tc * 32 + lt) * (BATCH * UNITS / 2)] = h;
        }
        __syncthreads();
        if (tc + 4 < 16) SCAN_LOAD(tc + 4);
    }
#undef SCAN_LOAD
}

// ---------------- launch ----------------
extern "C" void kernel_launch(void* const* d_in, const int* in_sizes, int n_in,
                              void* d_out, int out_size) {
    const float* x    = (const float*)d_in[0];
    const float* T    = (const float*)d_in[1];
    const float* B    = (const float*)d_in[2];
    const float* bias = (const float*)d_in[3];
    const float* h0   = (const float*)d_in[4];
    float* out        = (float*)d_out;
    (void)in_sizes; (void)n_in; (void)out_size;

    cudaFuncSetAttribute(gemm_persist_kernel, cudaFuncAttributeMaxDynamicSharedMemorySize,
                         2 * TS_STAGE);
    cudaFuncSetAttribute(scan_kernel, cudaFuncAttributeMaxDynamicSharedMemorySize, 65536);

    convert_x_kernel<<<(ROWS_T * DIN / 4) / 256, 256>>>(x);      // 4352 CTAs (tensor rows)
    convert_T_kernel<<<(DIN * UNITS) / 256, 256>>>(T);           // 512 CTAs (+zero queues)

    gemm_persist_kernel<<<296, 256, 2 * TS_STAGE>>>(x, T);       // 2 CTAs/SM, paired roles

    dim3 gs(UNITS / 128, BATCH);                                 // (4, 64)
    scan_kernel<<<gs, 64, 65536>>>(B, bias, h0, out);
}

// round 15
// speedup vs baseline: 1.6718x; 1.6718x over previous
#include <cuda_runtime.h>
#include <cuda_bf16.h>
#include <cstdint>

#define BATCH 64
#define SEQ   512
#define DIN   256
#define UNITS 512
#define M_TOT (BATCH * SEQ)   // 32768

// ---------------- scratch (module-static, no allocation APIs) ----------------
__device__ float         g_xT[(size_t)M_TOT * UNITS];   // 64 MB, row-major [M][512]
__device__ __nv_bfloat16 g_Bh[(size_t)UNITS * DIN];     // 256 KB, [N][K] (T transposed)
__device__ __nv_bfloat16 g_Bl[(size_t)UNITS * DIN];

// ---------------- PTX helpers ----------------
static __device__ __forceinline__ uint32_t smem_u32(const void* p) {
    uint32_t a;
    asm("{ .reg .u64 t; cvta.to.shared.u64 t, %1; cvt.u32.u64 %0, t; }" : "=r"(a) : "l"(p));
    return a;
}
static __device__ __forceinline__ void cp16(uint32_t dst, const void* src) {
    asm volatile("cp.async.cg.shared.global [%0], [%1], 16;" :: "r"(dst), "l"(src));
}
static __device__ __forceinline__ void cp_commit() { asm volatile("cp.async.commit_group;"); }
template <int N> static __device__ __forceinline__ void cp_wait() {
    asm volatile("cp.async.wait_group %0;" :: "n"(N));
}
static __device__ __forceinline__ void ldmx4(uint32_t& r0, uint32_t& r1,
                                             uint32_t& r2, uint32_t& r3, uint32_t addr) {
    asm volatile("ldmatrix.sync.aligned.m8n8.x4.shared.b16 {%0,%1,%2,%3}, [%4];"
                 : "=r"(r0), "=r"(r1), "=r"(r2), "=r"(r3) : "r"(addr));
}
static __device__ __forceinline__ void mma16816(float* c, const uint32_t* a,
                                                uint32_t b0, uint32_t b1) {
    asm volatile(
        "mma.sync.aligned.m16n8k16.row.col.f32.bf16.bf16.f32 "
        "{%0,%1,%2,%3}, {%4,%5,%6,%7}, {%8,%9}, {%0,%1,%2,%3};"
        : "+f"(c[0]), "+f"(c[1]), "+f"(c[2]), "+f"(c[3])
        : "r"(a[0]), "r"(a[1]), "r"(a[2]), "r"(a[3]), "r"(b0), "r"(b1));
}
// swizzled byte offset within a [rows][128B] tile (16B-aligned colb)
static __device__ __forceinline__ uint32_t sw_off(int row, int colb) {
    uint32_t off = (uint32_t)(row * 128 + colb);
    return off ^ ((off >> 3) & 0x70);
}
static __device__ __forceinline__ uint32_t sw_addr(uint32_t base, int row, int colb) {
    return base + sw_off(row, colb);
}

// split 8 fp32 -> 8 bf16-high (16B) + 8 bf16-low (16B)
static __device__ __forceinline__ void cvt8(const float4& a, const float4& b,
                                            uint4& hv, uint4& lv) {
    float f[8] = {a.x, a.y, a.z, a.w, b.x, b.y, b.z, b.w};
    unsigned short hs[8], ls[8];
#pragma unroll
    for (int j = 0; j < 8; j++) {
        __nv_bfloat16 h = __float2bfloat16_rn(f[j]);
        __nv_bfloat16 l = __float2bfloat16_rn(f[j] - __bfloat162float(h));
        hs[j] = *reinterpret_cast<unsigned short*>(&h);
        ls[j] = *reinterpret_cast<unsigned short*>(&l);
    }
    hv = make_uint4((uint32_t)hs[0] | ((uint32_t)hs[1] << 16),
                    (uint32_t)hs[2] | ((uint32_t)hs[3] << 16),
                    (uint32_t)hs[4] | ((uint32_t)hs[5] << 16),
                    (uint32_t)hs[6] | ((uint32_t)hs[7] << 16));
    lv = make_uint4((uint32_t)ls[0] | ((uint32_t)ls[1] << 16),
                    (uint32_t)ls[2] | ((uint32_t)ls[3] << 16),
                    (uint32_t)ls[4] | ((uint32_t)ls[5] << 16),
                    (uint32_t)ls[6] | ((uint32_t)ls[7] << 16));
}

// ---------------- T conversion (tiny) ----------------
__global__ __launch_bounds__(256)
void convert_T_kernel(const float* __restrict__ T) {
    int idx = blockIdx.x * 256 + threadIdx.x;   // idx = k*512 + n
    int k = idx >> 9;
    int n = idx & 511;
    float v = T[idx];
    __nv_bfloat16 h = __float2bfloat16_rn(v);
    __nv_bfloat16 l = __float2bfloat16_rn(v - __bfloat162float(h));
    g_Bh[(size_t)n * DIN + k] = h;
    g_Bl[(size_t)n * DIN + k] = l;
}

// ---------------- GEMM with fused A conversion ----------------
// g_xT = x @ T via split bf16 (Ah*Bh + Ah*Bl + Al*Bh). Tile 128x128, BK=64.
// A path: LDG fp32 (register prefetch) -> cvt -> STS (h+l swizzled smem).
// B path: cp.async double-buffered from pre-converted g_Bh/g_Bl.
// 256 threads, 8 warps (4m x 2n), warp tile 32x64 (proven 85us config).
// Stage (64KB): Ah@0, Al@16K, Bh@32K, Bl@48K.
#define GS_STAGE 65536

__global__ __launch_bounds__(256, 1)
void gemm_kernel(const float* __restrict__ xA) {
    extern __shared__ __align__(1024) char sm[];
    const uint32_t sbase = smem_u32(sm);
    const int tid = threadIdx.x;
    const int wid = tid >> 5, lid = tid & 31;
    const int warp_m = wid & 3;        // 4 m-groups of 32 rows
    const int warp_n = wid >> 2;       // 2 n-groups of 64 cols
    const int m0 = blockIdx.y * 128;
    const int n0 = blockIdx.x * 128;

    const int lrow = lid & 15;
    const int lqc  = (lid >> 4) * 16;
    const int arow0 = warp_m * 32 + lrow;
    const int brow0 = warp_n * 64 + lrow;

    // per-thread A segments: 4 segs of 8 consecutive k-floats
    // seg s = tid + i*256 (i<4): row = s>>3 (0..127), sg = s&7 -> k = sg*8
    float4 pa[4][2];

#define A_LDG(kc) do {                                                           \
        _Pragma("unroll")                                                        \
        for (int i = 0; i < 4; i++) {                                            \
            int s = tid + i * 256;                                               \
            int row = s >> 3, sg = s & 7;                                        \
            const float* p = xA + (size_t)(m0 + row) * DIN + (kc) * 64 + sg * 8; \
            pa[i][0] = *(const float4*)(p);                                      \
            pa[i][1] = *(const float4*)(p + 4);                                  \
        }                                                                        \
    } while (0)

#define A_STS(kc) do {                                                           \
        char* stg = sm + ((kc) & 1) * GS_STAGE;                                  \
        _Pragma("unroll")                                                        \
        for (int i = 0; i < 4; i++) {                                            \
            int s = tid + i * 256;                                               \
            int row = s >> 3, sg = s & 7;                                        \
            uint4 hv, lv;                                                        \
            cvt8(pa[i][0], pa[i][1], hv, lv);                                    \
            uint32_t so = sw_off(row, sg * 16);                                  \
            *(uint4*)(stg + so)         = hv;                                    \
            *(uint4*)(stg + 16384 + so) = lv;                                    \
        }                                                                        \
    } while (0)

#define B_LOAD(kc) do {                                                          \
        const uint32_t _sb = sbase + ((kc) & 1) * GS_STAGE + 32768;              \
        const int _k0b = (kc) * 128;                                             \
        _Pragma("unroll")                                                        \
        for (int t = 0; t < 2; t++) {                                            \
            const char* g = (const char*)(t ? g_Bl : g_Bh) + (size_t)n0 * 512;   \
            _Pragma("unroll")                                                    \
            for (int i = 0; i < 4; i++) {                                        \
                int u = tid + i * 256;                                           \
                int row = u >> 3, ku = u & 7;                                    \
                cp16(_sb + t * 16384 + sw_off(row, ku * 16),                     \
                     g + (size_t)row * 512 + _k0b + ku * 16);                    \
            }                                                                    \
        }                                                                        \
        cp_commit();                                                             \
    } while (0)

    float acc[2][8][4];
#pragma unroll
    for (int i = 0; i < 2; i++)
#pragma unroll
        for (int j = 0; j < 8; j++)
#pragma unroll
            for (int q = 0; q < 4; q++) acc[i][j][q] = 0.0f;

    // prologue
    A_LDG(0);
    A_STS(0);
    B_LOAD(0);
    A_LDG(1);          // held in regs until after MMA(0)
    B_LOAD(1);

#pragma unroll
    for (int kc = 0; kc < 4; kc++) {
        if (kc < 3) cp_wait<1>(); else cp_wait<0>();
        __syncthreads();
        const uint32_t sb = sbase + (kc & 1) * GS_STAGE;
        // pass 0: Ah*Bh, 1: Ah*Bl, 2: Al*Bh
        const uint32_t aB[3] = {sb, sb, sb + 16384};
        const uint32_t bB[3] = {sb + 32768, sb + 49152, sb + 32768};

#pragma unroll
        for (int s = 0; s < 12; s++) {
            const uint32_t aS = aB[s >> 2], bS = bB[s >> 2];
            const int kb = (s & 3) * 32 + lqc;
            uint32_t a[2][4], b[8][2];
#pragma unroll
            for (int mt = 0; mt < 2; mt++)
                ldmx4(a[mt][0], a[mt][1], a[mt][2], a[mt][3],
                      sw_addr(aS, arow0 + mt * 16, kb));
#pragma unroll
            for (int ng = 0; ng < 4; ng++) {
                uint32_t r0, r1, r2, r3;
                ldmx4(r0, r1, r2, r3, sw_addr(bS, brow0 + ng * 16, kb));
                b[2 * ng][0] = r0; b[2 * ng + 1][0] = r1;
                b[2 * ng][1] = r2; b[2 * ng + 1][1] = r3;
            }
#pragma unroll
            for (int mt = 0; mt < 2; mt++)
#pragma unroll
                for (int nt = 0; nt < 8; nt++)
                    mma16816(acc[mt][nt], a[mt], b[nt][0], b[nt][1]);
        }

        // stage (kc+1)&1 was last read by MMA(kc-1), finished before this iter's
        // sync -> safe to overwrite now. STS A(kc+1) from regs, then prefetch.
        if (kc < 3) {
            A_STS(kc + 1);
            if (kc < 2) {
                A_LDG(kc + 2);
                B_LOAD(kc + 2);
            }
        }
    }
#undef A_LDG
#undef A_STS
#undef B_LOAD

    // Epilogue: write c-fragments directly.
    const int gID = lid >> 2, tg = lid & 3;
#pragma unroll
    for (int mt = 0; mt < 2; mt++) {
#pragma unroll
        for (int nt = 0; nt < 8; nt++) {
            int m_lo = m0 + warp_m * 32 + mt * 16 + gID;
            int n    = n0 + warp_n * 64 + nt * 8 + tg * 2;
            *(float2*)(g_xT + (size_t)m_lo * UNITS + n) =
                make_float2(acc[mt][nt][0], acc[mt][nt][1]);
            *(float2*)(g_xT + (size_t)(m_lo + 8) * UNITS + n) =
                make_float2(acc[mt][nt][2], acc[mt][nt][3]);
        }
    }
}

// ---------------- scan kernel (R8-proven, 23.2us): 2x2-block recurrence ----------------
__global__ __launch_bounds__(64, 1)
void scan_kernel(const float* __restrict__ Bfull, const float* __restrict__ bias,
                 const float* __restrict__ h0, float* __restrict__ out) {
    extern __shared__ __align__(1024) char sm[];   // 4 x 16KB
    const uint32_t sbase = smem_u32(sm);
    const int tid = threadIdx.x;
    const int b = blockIdx.y;
    const int u0 = blockIdx.x * 128;
    const int u = u0 + 2 * tid;

    const float B00 = Bfull[(size_t)u * UNITS + u];
    const float B01 = Bfull[(size_t)u * UNITS + u + 1];
    const float B10 = Bfull[(size_t)(u + 1) * UNITS + u];
    const float B11 = Bfull[(size_t)(u + 1) * UNITS + u + 1];
    const float2 bi = *(const float2*)(bias + u);
    float2 h = *(const float2*)(h0 + u);

    const float* xbase = g_xT + (size_t)b * SEQ * UNITS + u0;

#define SCAN_LOAD(tc) do {                                                       \
        uint32_t dst = sbase + ((tc) & 3) * 16384;                               \
        const float* src = xbase + (size_t)(tc) * 32 * UNITS;                    \
        _Pragma("unroll")                                                        \
        for (int i = 0; i < 16; i++) {                                           \
            int uq = tid + i * 64;                                               \
            int row = uq >> 5, cu = uq & 31;                                     \
            cp16(dst + row * 512 + cu * 16, src + (size_t)row * UNITS + cu * 4); \
        }                                                                        \
        cp_commit();                                                             \
    } while (0)

    SCAN_LOAD(0);
    SCAN_LOAD(1);
    SCAN_LOAD(2);
    SCAN_LOAD(3);

    float2* op = (float2*)(out + (size_t)b * UNITS + u0) + tid;

    for (int tc = 0; tc < 16; tc++) {
        if (tc < 12) cp_wait<3>(); else cp_wait<0>();
        __syncthreads();
        const float2* xs = (const float2*)(sm + (tc & 3) * 16384) + tid;
#pragma unroll
        for (int lt = 0; lt < 32; lt++) {
            float2 xv = xs[lt * 64];
            float z0 = fmaf(h.y, B10, fmaf(h.x, B00, xv.x));
            float z1 = fmaf(h.y, B11, fmaf(h.x, B01, xv.y));
            float m0 = fmaxf(fabsf(z0) + bi.x, 0.0f);
            float m1 = fmaxf(fabsf(z1) + bi.y, 0.0f);
            h.x = (z0 > 0.0f) ? m0 : ((z0 < 0.0f) ? -m0 : 0.0f);
            h.y = (z1 > 0.0f) ? m1 : ((z1 < 0.0f) ? -m1 : 0.0f);
            op[(size_t)(tc * 32 + lt) * (BATCH * UNITS / 2)] = h;
        }
        __syncthreads();
        if (tc + 4 < 16) SCAN_LOAD(tc + 4);
    }
#undef SCAN_LOAD
}

// ---------------- launch ----------------
extern "C" void kernel_launch(void* const* d_in, const int* in_sizes, int n_in,
                              void* d_out, int out_size) {
    const float* x    = (const float*)d_in[0];
    const float* T    = (const float*)d_in[1];
    const float* B    = (const float*)d_in[2];
    const float* bias = (const float*)d_in[3];
    const float* h0   = (const float*)d_in[4];
    float* out        = (float*)d_out;
    (void)in_sizes; (void)n_in; (void)out_size;

    cudaFuncSetAttribute(gemm_kernel, cudaFuncAttributeMaxDynamicSharedMemorySize,
                         2 * GS_STAGE);
    cudaFuncSetAttribute(scan_kernel, cudaFuncAttributeMaxDynamicSharedMemorySize, 65536);

    convert_T_kernel<<<(DIN * UNITS) / 256, 256>>>(T);           // 512 CTAs (~0.5us)

    dim3 gg(UNITS / 128, M_TOT / 128);                           // (4, 256)
    gemm_kernel<<<gg, 256, 2 * GS_STAGE>>>(x);                   // fused A conversion

    dim3 gs(UNITS / 128, BATCH);                                 // (4, 64)
    scan_kernel<<<gs, 64, 65536>>>(B, bias, h0, out);
}